// round 2
// baseline (speedup 1.0000x reference)
#include <cuda_runtime.h>
#include <math.h>

#define Bsz 2
#define Nn  1024
#define Dd  512
#define Hh  16
#define DHd 32

typedef unsigned long long u64;

// Scratch (device globals; no allocation allowed)
__device__ float g_q[Bsz*Hh*Nn*DHd];     // [B,H,N,DH]
__device__ float g_k[Bsz*Hh*Nn*DHd];     // [B,H,N,DH]
__device__ float g_v[Bsz*Hh*Nn*DHd];     // [B,H,N,DH]
__device__ float g_att[Bsz*Nn*Dd];       // [B,N,H*DH]
__device__ float g_y[Bsz*Nn*Dd];         // pre-LN residual

// ---- packed fp32 helpers (sm_103a f32x2 pipe) ------------------------------
__device__ __forceinline__ u64 pack2(float lo, float hi) {
    u64 r;
    asm("mov.b64 %0, {%1, %2};" : "=l"(r) : "f"(lo), "f"(hi));
    return r;
}
__device__ __forceinline__ float2 unpack2(u64 v) {
    float2 r;
    asm("mov.b64 {%0, %1}, %2;" : "=f"(r.x), "=f"(r.y) : "l"(v));
    return r;
}
#define FMA2(acc, a, b) \
    asm("fma.rn.f32x2 %0, %1, %2, %0;" : "+l"(acc) : "l"(a), "l"(b))

// ---------------------------------------------------------------------------
// Kernel 1: QKV GEMM.  C[m,o] = sum_k x[m,k]*att_w[o,k]
// M=2048, O=1536, K=512. Block tile 64(m) x 128(o), 256 thr, microtile 4x8.
// W tile stored duplicated (w,w) as u64 so inner loop is pure FMA2.
// ---------------------------------------------------------------------------
__global__ __launch_bounds__(256) void gemm_qkv_kernel(
    const float* __restrict__ x, const float* __restrict__ w)
{
    __shared__ float As[16][64 + 4];
    __shared__ u64   Wd[16][128 + 2];
    const int tid = threadIdx.x;
    const int m0 = blockIdx.y * 64;
    const int o0 = blockIdx.x * 128;
    const int tx = tid & 15, ty = tid >> 4;

    u64 acc[2][8] = {};

    for (int k0 = 0; k0 < 512; k0 += 16) {
        {   // A tile: 64x16 floats, 1 float4/thread
            int row = tid >> 2, c4 = (tid & 3) * 4;
            float4 v = *(const float4*)&x[(m0 + row) * 512 + k0 + c4];
            As[c4+0][row] = v.x; As[c4+1][row] = v.y;
            As[c4+2][row] = v.z; As[c4+3][row] = v.w;
        }
        #pragma unroll
        for (int r = 0; r < 2; r++) {  // W tile: 128x16, duplicated
            int e = tid + r * 256;
            int row = e >> 2, c4 = (e & 3) * 4;
            float4 v = *(const float4*)&w[(o0 + row) * 512 + k0 + c4];
            Wd[c4+0][row] = pack2(v.x, v.x);
            Wd[c4+1][row] = pack2(v.y, v.y);
            Wd[c4+2][row] = pack2(v.z, v.z);
            Wd[c4+3][row] = pack2(v.w, v.w);
        }
        __syncthreads();
        #pragma unroll
        for (int kk = 0; kk < 16; kk++) {
            u64 a2[2];
            {
                ulonglong2 t0 = *(const ulonglong2*)&As[kk][ty * 4];
                a2[0] = t0.x; a2[1] = t0.y;
            }
            u64 w2[8];
            {
                const ulonglong2* wp = (const ulonglong2*)&Wd[kk][tx * 8];
                ulonglong2 w0 = wp[0], w1 = wp[1], ww2 = wp[2], w3 = wp[3];
                w2[0]=w0.x; w2[1]=w0.y; w2[2]=w1.x; w2[3]=w1.y;
                w2[4]=ww2.x; w2[5]=ww2.y; w2[6]=w3.x; w2[7]=w3.y;
            }
            #pragma unroll
            for (int i2 = 0; i2 < 2; i2++)
                #pragma unroll
                for (int j = 0; j < 8; j++)
                    FMA2(acc[i2][j], a2[i2], w2[j]);
        }
        __syncthreads();
    }

    // Epilogue: scatter into q/k/v [B,H,N,DH]; per thread all 8 cols share head.
    int o_base = o0 + tx * 8;
    int which = o_base >> 9;
    int h = (o_base >> 5) & 15;
    int d = o_base & 31;
    float* dst = (which == 0) ? g_q : ((which == 1) ? g_k : g_v);
    #pragma unroll
    for (int i2 = 0; i2 < 2; i2++) {
        int m = m0 + ty * 4 + i2 * 2;
        int bb = m >> 10, ir = m & 1023;
        float* base = &dst[((bb * Hh + h) * Nn + ir) * DHd + d];
        float2 f[8];
        #pragma unroll
        for (int j = 0; j < 8; j++) f[j] = unpack2(acc[i2][j]);
        float4 r0a = make_float4(f[0].x, f[1].x, f[2].x, f[3].x);
        float4 r0b = make_float4(f[4].x, f[5].x, f[6].x, f[7].x);
        float4 r1a = make_float4(f[0].y, f[1].y, f[2].y, f[3].y);
        float4 r1b = make_float4(f[4].y, f[5].y, f[6].y, f[7].y);
        *(float4*)(base)      = r0a;
        *(float4*)(base + 4)  = r0b;
        *(float4*)(base + 32) = r1a;   // row m+1 (same batch: m even)
        *(float4*)(base + 36) = r1b;
    }
}

// ---------------------------------------------------------------------------
// Kernel 2: Fused attention, f32x2 inner loops, no online-max softmax.
// Block = 64 queries x (head, batch); thread owns one query row.
// Scores bounded (|s| <~ 30) so direct exp accumulation is safe in fp32.
// ---------------------------------------------------------------------------
__global__ __launch_bounds__(64) void attn_kernel(
    const float* __restrict__ pdist, const float* __restrict__ angle,
    const float* __restrict__ adj,   const unsigned char* __restrict__ mask,
    const float* __restrict__ gamma_p, const float* __restrict__ gamma_adj,
    const float* __restrict__ w_bias)
{
    const int b = blockIdx.z;
    const int h = blockIdx.y;
    const int t = threadIdx.x;
    const int i = blockIdx.x * 64 + t;

    __shared__ float sK[32][32];
    __shared__ float sV[32][32];

    const float SCALE = 0.17677669529663689f;  // 1/sqrt(32)
    u64 q2[16];
    {
        const float4* q4 = (const float4*)&g_q[(((b*Hh + h)*Nn) + i)*DHd];
        #pragma unroll
        for (int c = 0; c < 8; c++) {
            float4 v = q4[c];
            q2[2*c]   = pack2(v.x * SCALE, v.y * SCALE);
            q2[2*c+1] = pack2(v.z * SCALE, v.w * SCALE);
        }
    }
    const float gp  = gamma_p[h];
    const float ga  = gamma_adj[h];
    const float wb0 = w_bias[h*2+0];
    const float wb1 = w_bias[h*2+1];

    const float* Kb = &g_k[((b*Hh + h)*Nn)*DHd];
    const float* Vb = &g_v[((b*Hh + h)*Nn)*DHd];
    const float* pd = pdist + (b*Nn + i)*Nn;
    const float* aj = adj   + (b*Nn + i)*Nn;
    const float* an = angle + (size_t)(b*Nn + i)*Nn*2;
    const unsigned char* mk = mask + b*Nn;

    u64 acc[16] = {};
    float l = 0.f;

    for (int j0 = 0; j0 < Nn; j0 += 32) {
        __syncthreads();
        {   // cooperative K/V tile load: contiguous 4KB each
            const float4* gK = (const float4*)(Kb + j0*DHd);
            const float4* gV = (const float4*)(Vb + j0*DHd);
            float4* dK = (float4*)sK;
            float4* dV = (float4*)sV;
            #pragma unroll
            for (int r = 0; r < 4; r++) {
                dK[t + 64*r] = gK[t + 64*r];
                dV[t + 64*r] = gV[t + 64*r];
            }
        }
        __syncthreads();

        float p[32];
        const float4* pdp = (const float4*)(pd + j0);
        const float4* ajp = (const float4*)(aj + j0);
        const float4* anp = (const float4*)(an + 2*j0);
        #pragma unroll
        for (int c8 = 0; c8 < 4; c8++) {
            float pdv[8], ajv[8], anv[16];
            *(float4*)&pdv[0]  = pdp[2*c8];     *(float4*)&pdv[4]  = pdp[2*c8+1];
            *(float4*)&ajv[0]  = ajp[2*c8];     *(float4*)&ajv[4]  = ajp[2*c8+1];
            *(float4*)&anv[0]  = anp[4*c8];     *(float4*)&anv[4]  = anp[4*c8+1];
            *(float4*)&anv[8]  = anp[4*c8+2];   *(float4*)&anv[12] = anp[4*c8+3];
            #pragma unroll
            for (int jj = 0; jj < 8; jj++) {
                const int j = c8*8 + jj;
                u64 sa = 0, sb = 0;
                const u64* k2 = (const u64*)sK[j];
                #pragma unroll
                for (int c = 0; c < 16; c += 2) {
                    FMA2(sa, q2[c],   k2[c]);
                    FMA2(sb, q2[c+1], k2[c+1]);
                }
                float2 fa = unpack2(sa), fb = unpack2(sb);
                float s = (fa.x + fa.y) + (fb.x + fb.y);
                s = fmaf(wb0, anv[2*jj],   s);
                s = fmaf(wb1, anv[2*jj+1], s);
                s = fmaf(ga,  ajv[jj],     s);
                s = fmaf(-gp, pdv[jj],     s);
                if (mk[j0 + j]) s = -1e9f;
                float e = __expf(s);
                l += e;
                p[j] = e;
            }
        }
        #pragma unroll
        for (int j = 0; j < 32; j++) {
            u64 p2 = pack2(p[j], p[j]);
            const u64* v2 = (const u64*)sV[j];
            #pragma unroll
            for (int c = 0; c < 16; c++)
                FMA2(acc[c], p2, v2[c]);
        }
    }

    const float inv = 1.0f / l;
    float* outp = &g_att[(size_t)(b*Nn + i)*Dd + h*DHd];
    #pragma unroll
    for (int c = 0; c < 8; c++) {
        float2 f0 = unpack2(acc[2*c]);
        float2 f1 = unpack2(acc[2*c+1]);
        ((float4*)outp)[c] = make_float4(f0.x*inv, f0.y*inv, f1.x*inv, f1.y*inv);
    }
}

// ---------------------------------------------------------------------------
// Kernel 3: FF GEMM + residual + bias.  y = x + ffb + att @ ff_w^T
// M=2048, O=512, K=512. Tile 64x128, microtile 4x8, f32x2.
// ---------------------------------------------------------------------------
__global__ __launch_bounds__(256) void gemm_ff_kernel(
    const float* __restrict__ w, const float* __restrict__ xres,
    const float* __restrict__ ffb)
{
    __shared__ float As[16][64 + 4];
    __shared__ u64   Wd[16][128 + 2];
    const int tid = threadIdx.x;
    const int m0 = blockIdx.y * 64;
    const int o0 = blockIdx.x * 128;
    const int tx = tid & 15, ty = tid >> 4;

    u64 acc[2][8] = {};

    for (int k0 = 0; k0 < 512; k0 += 16) {
        {
            int row = tid >> 2, c4 = (tid & 3) * 4;
            float4 v = *(const float4*)&g_att[(m0 + row) * 512 + k0 + c4];
            As[c4+0][row] = v.x; As[c4+1][row] = v.y;
            As[c4+2][row] = v.z; As[c4+3][row] = v.w;
        }
        #pragma unroll
        for (int r = 0; r < 2; r++) {
            int e = tid + r * 256;
            int row = e >> 2, c4 = (e & 3) * 4;
            float4 v = *(const float4*)&w[(o0 + row) * 512 + k0 + c4];
            Wd[c4+0][row] = pack2(v.x, v.x);
            Wd[c4+1][row] = pack2(v.y, v.y);
            Wd[c4+2][row] = pack2(v.z, v.z);
            Wd[c4+3][row] = pack2(v.w, v.w);
        }
        __syncthreads();
        #pragma unroll
        for (int kk = 0; kk < 16; kk++) {
            u64 a2[2];
            {
                ulonglong2 t0 = *(const ulonglong2*)&As[kk][ty * 4];
                a2[0] = t0.x; a2[1] = t0.y;
            }
            u64 w2[8];
            {
                const ulonglong2* wp = (const ulonglong2*)&Wd[kk][tx * 8];
                ulonglong2 w0 = wp[0], w1 = wp[1], ww2 = wp[2], w3 = wp[3];
                w2[0]=w0.x; w2[1]=w0.y; w2[2]=w1.x; w2[3]=w1.y;
                w2[4]=ww2.x; w2[5]=ww2.y; w2[6]=w3.x; w2[7]=w3.y;
            }
            #pragma unroll
            for (int i2 = 0; i2 < 2; i2++)
                #pragma unroll
                for (int j = 0; j < 8; j++)
                    FMA2(acc[i2][j], a2[i2], w2[j]);
        }
        __syncthreads();
    }

    int o_base = o0 + tx * 8;
    float4 fb0 = *(const float4*)&ffb[o_base];
    float4 fb1 = *(const float4*)&ffb[o_base + 4];
    #pragma unroll
    for (int i2 = 0; i2 < 2; i2++) {
        int m = m0 + ty * 4 + i2 * 2;
        float2 f[8];
        #pragma unroll
        for (int j = 0; j < 8; j++) f[j] = unpack2(acc[i2][j]);
        #pragma unroll
        for (int r = 0; r < 2; r++) {
            int row = m + r;
            float4 x0 = *(const float4*)&xres[row*512 + o_base];
            float4 x1 = *(const float4*)&xres[row*512 + o_base + 4];
            float4 o0v, o1v;
            if (r == 0) {
                o0v = make_float4(f[0].x, f[1].x, f[2].x, f[3].x);
                o1v = make_float4(f[4].x, f[5].x, f[6].x, f[7].x);
            } else {
                o0v = make_float4(f[0].y, f[1].y, f[2].y, f[3].y);
                o1v = make_float4(f[4].y, f[5].y, f[6].y, f[7].y);
            }
            o0v.x += x0.x + fb0.x; o0v.y += x0.y + fb0.y;
            o0v.z += x0.z + fb0.z; o0v.w += x0.w + fb0.w;
            o1v.x += x1.x + fb1.x; o1v.y += x1.y + fb1.y;
            o1v.z += x1.z + fb1.z; o1v.w += x1.w + fb1.w;
            *(float4*)&g_y[row*512 + o_base]     = o0v;
            *(float4*)&g_y[row*512 + o_base + 4] = o1v;
        }
    }
}

// ---------------------------------------------------------------------------
// Kernel 4: LayerNorm rows of g_y -> out.
// ---------------------------------------------------------------------------
__global__ __launch_bounds__(128) void ln_kernel(
    const float* __restrict__ lnw, const float* __restrict__ lnb,
    float* __restrict__ out)
{
    const int row = blockIdx.x;
    const int t = threadIdx.x;
    const float4 v = ((const float4*)&g_y[(size_t)row*512])[t];

    float s  = v.x + v.y + v.z + v.w;
    float ss = v.x*v.x + v.y*v.y + v.z*v.z + v.w*v.w;

    __shared__ float rs[4], rss[4];
    #pragma unroll
    for (int off = 16; off > 0; off >>= 1) {
        s  += __shfl_down_sync(0xffffffffu, s,  off);
        ss += __shfl_down_sync(0xffffffffu, ss, off);
    }
    if ((t & 31) == 0) { rs[t >> 5] = s; rss[t >> 5] = ss; }
    __syncthreads();
    float sum  = rs[0]  + rs[1]  + rs[2]  + rs[3];
    float sums = rss[0] + rss[1] + rss[2] + rss[3];

    const float mu   = sum  * (1.0f/512.0f);
    const float var  = sums * (1.0f/512.0f) - mu*mu;
    const float rstd = rsqrtf(var + 1e-5f);

    const float4 w = ((const float4*)lnw)[t];
    const float4 b = ((const float4*)lnb)[t];
    float4 o;
    o.x = (v.x - mu)*rstd*w.x + b.x;
    o.y = (v.y - mu)*rstd*w.y + b.y;
    o.z = (v.z - mu)*rstd*w.z + b.z;
    o.w = (v.w - mu)*rstd*w.w + b.w;
    ((float4*)&out[(size_t)row*512])[t] = o;
}

// ---------------------------------------------------------------------------
extern "C" void kernel_launch(void* const* d_in, const int* in_sizes, int n_in,
                              void* d_out, int out_size)
{
    const float* x         = (const float*)d_in[0];
    const float* pdist     = (const float*)d_in[1];
    const float* angle     = (const float*)d_in[2];
    const float* adj       = (const float*)d_in[3];
    const unsigned char* mask = (const unsigned char*)d_in[4];
    const float* gamma_p   = (const float*)d_in[5];
    const float* gamma_adj = (const float*)d_in[6];
    const float* w_bias    = (const float*)d_in[7];
    const float* att_w     = (const float*)d_in[8];
    const float* ff_w      = (const float*)d_in[9];
    const float* ff_b      = (const float*)d_in[10];
    const float* ln_w      = (const float*)d_in[11];
    const float* ln_b      = (const float*)d_in[12];
    float* out = (float*)d_out;

    gemm_qkv_kernel<<<dim3(1536/128, 2048/64), 256>>>(x, att_w);
    attn_kernel<<<dim3(Nn/64, Hh, Bsz), 64>>>(pdist, angle, adj, mask,
                                              gamma_p, gamma_adj, w_bias);
    gemm_ff_kernel<<<dim3(512/128, 2048/64), 256>>>(ff_w, x, ff_b);
    ln_kernel<<<Bsz*Nn, 128>>>(ln_w, ln_b, out);
}

// round 3
// speedup vs baseline: 2.1302x; 2.1302x over previous
#include <cuda_runtime.h>
#include <math.h>

#define Bsz 2
#define Nn  1024
#define Dd  512
#define Hh  16
#define DHd 32

// Scratch (device globals; no allocation allowed)
__device__ float g_q[Bsz*Hh*Nn*DHd];     // [B,H,N,DH]
__device__ float g_k[Bsz*Hh*Nn*DHd];     // [B,H,N,DH]
__device__ float g_v[Bsz*Hh*Nn*DHd];     // [B,H,N,DH]
__device__ float g_att[Bsz*Nn*Dd];       // [B,N,H*DH]
__device__ float g_y[Bsz*Nn*Dd];         // pre-LN residual

// ---------------------------------------------------------------------------
// Kernel 1: QKV GEMM.  C[m,o] = sum_k x[m,k]*att_w[o,k]
// M=2048, O=1536, K=512. Tile 128x128, 256 threads, 8x8 microtile.
// Epilogue scatters float4s into g_q/g_k/g_v [B,H,N,DH].
// ---------------------------------------------------------------------------
__global__ __launch_bounds__(256) void gemm_qkv_kernel(
    const float* __restrict__ x, const float* __restrict__ w)
{
    __shared__ float As[16][132];
    __shared__ float Bs[16][132];
    const int tid = threadIdx.x;
    const int m0 = blockIdx.y * 128;
    const int o0 = blockIdx.x * 128;
    const int tx = tid & 15, ty = tid >> 4;

    float acc[8][8] = {};

    for (int k0 = 0; k0 < 512; k0 += 16) {
        #pragma unroll
        for (int r = 0; r < 2; r++) {
            int e = tid + r * 256;
            int row = e >> 2, c4 = (e & 3) << 2;
            float4 a = *(const float4*)&x[(m0 + row) * 512 + k0 + c4];
            As[c4+0][row] = a.x; As[c4+1][row] = a.y;
            As[c4+2][row] = a.z; As[c4+3][row] = a.w;
            float4 b = *(const float4*)&w[(o0 + row) * 512 + k0 + c4];
            Bs[c4+0][row] = b.x; Bs[c4+1][row] = b.y;
            Bs[c4+2][row] = b.z; Bs[c4+3][row] = b.w;
        }
        __syncthreads();
        #pragma unroll
        for (int kk = 0; kk < 16; kk++) {
            float a[8], b[8];
            *(float4*)&a[0] = *(const float4*)&As[kk][ty*8];
            *(float4*)&a[4] = *(const float4*)&As[kk][ty*8+4];
            *(float4*)&b[0] = *(const float4*)&Bs[kk][tx*8];
            *(float4*)&b[4] = *(const float4*)&Bs[kk][tx*8+4];
            #pragma unroll
            for (int i = 0; i < 8; i++)
                #pragma unroll
                for (int j = 0; j < 8; j++)
                    acc[i][j] = fmaf(a[i], b[j], acc[i][j]);
        }
        __syncthreads();
    }

    // Epilogue: 8 columns per thread share one (which, head, d) group.
    const int o_base = o0 + tx * 8;
    const int which = o_base >> 9;
    const int h = (o_base >> 5) & 15;
    const int d = o_base & 31;
    float* dst = (which == 0) ? g_q : ((which == 1) ? g_k : g_v);
    #pragma unroll
    for (int i = 0; i < 8; i++) {
        int m = m0 + ty * 8 + i;
        int bb = m >> 10, ir = m & 1023;
        float* base = &dst[((bb * Hh + h) * Nn + ir) * DHd + d];
        *(float4*)(base)     = make_float4(acc[i][0], acc[i][1], acc[i][2], acc[i][3]);
        *(float4*)(base + 4) = make_float4(acc[i][4], acc[i][5], acc[i][6], acc[i][7]);
    }
}

// ---------------------------------------------------------------------------
// Kernel 2: Fused attention. Block = 64 queries x (head,batch), 128 threads:
// 2 threads per query, each owns 16 of 32 dims. One shfl_xor combines the
// score halves. Direct exp (scores bounded), fused exp + PV accumulate.
// ---------------------------------------------------------------------------
__global__ __launch_bounds__(128) void attn_kernel(
    const float* __restrict__ pdist, const float* __restrict__ angle,
    const float* __restrict__ adj,   const unsigned char* __restrict__ mask,
    const float* __restrict__ gamma_p, const float* __restrict__ gamma_adj,
    const float* __restrict__ w_bias)
{
    const int b = blockIdx.z;
    const int h = blockIdx.y;
    const int t = threadIdx.x;
    const int qi = t >> 1;           // query within block
    const int half = t & 1;          // which 16-dim half
    const int i = blockIdx.x * 64 + qi;

    __shared__ float sK[32][32];
    __shared__ float sV[32][32];

    const float SCALE = 0.17677669529663689f;  // 1/sqrt(32)
    float q[16];
    {
        const float4* q4 = (const float4*)&g_q[(((b*Hh + h)*Nn) + i)*DHd + half*16];
        #pragma unroll
        for (int c = 0; c < 4; c++) {
            float4 v = q4[c];
            q[c*4+0] = v.x * SCALE; q[c*4+1] = v.y * SCALE;
            q[c*4+2] = v.z * SCALE; q[c*4+3] = v.w * SCALE;
        }
    }
    const float gp  = gamma_p[h];
    const float ga  = gamma_adj[h];
    const float wb0 = w_bias[h*2+0];
    const float wb1 = w_bias[h*2+1];

    const float* Kb = &g_k[((b*Hh + h)*Nn)*DHd];
    const float* Vb = &g_v[((b*Hh + h)*Nn)*DHd];
    const float* pd = pdist + (b*Nn + i)*Nn;
    const float* aj = adj   + (b*Nn + i)*Nn;
    const float* an = angle + (size_t)(b*Nn + i)*Nn*2;
    const unsigned char* mk = mask + b*Nn;

    float acc[16] = {};
    float l = 0.f;

    for (int j0 = 0; j0 < Nn; j0 += 32) {
        __syncthreads();
        {   // cooperative tile load: 1024 floats each = 2 float4/thread
            const float4* gK = (const float4*)(Kb + j0*DHd);
            const float4* gV = (const float4*)(Vb + j0*DHd);
            float4* dK = (float4*)sK;
            float4* dV = (float4*)sV;
            dK[t]       = gK[t];
            dK[t + 128] = gK[t + 128];
            dV[t]       = gV[t];
            dV[t + 128] = gV[t + 128];
        }
        __syncthreads();

        const float4* pdp = (const float4*)(pd + j0);
        const float4* ajp = (const float4*)(aj + j0);
        const float4* anp = (const float4*)(an + 2*j0);
        #pragma unroll
        for (int c8 = 0; c8 < 4; c8++) {
            float pdv[8], ajv[8], anv[16];
            *(float4*)&pdv[0]  = pdp[2*c8];     *(float4*)&pdv[4]  = pdp[2*c8+1];
            *(float4*)&ajv[0]  = ajp[2*c8];     *(float4*)&ajv[4]  = ajp[2*c8+1];
            *(float4*)&anv[0]  = anp[4*c8];     *(float4*)&anv[4]  = anp[4*c8+1];
            *(float4*)&anv[8]  = anp[4*c8+2];   *(float4*)&anv[12] = anp[4*c8+3];
            #pragma unroll
            for (int jj = 0; jj < 8; jj++) {
                const int j = c8*8 + jj;
                // partial dot over this thread's 16 dims
                const float4* kp = (const float4*)&sK[j][half*16];
                float s = 0.f;
                #pragma unroll
                for (int c = 0; c < 4; c++) {
                    float4 kv = kp[c];
                    s = fmaf(q[c*4+0], kv.x, s);
                    s = fmaf(q[c*4+1], kv.y, s);
                    s = fmaf(q[c*4+2], kv.z, s);
                    s = fmaf(q[c*4+3], kv.w, s);
                }
                s += __shfl_xor_sync(0xffffffffu, s, 1);
                s = fmaf(wb0, anv[2*jj],   s);
                s = fmaf(wb1, anv[2*jj+1], s);
                s = fmaf(ga,  ajv[jj],     s);
                s = fmaf(-gp, pdv[jj],     s);
                if (mk[j0 + j]) s = -1e9f;
                float e = __expf(s);
                l += e;
                const float4* vp = (const float4*)&sV[j][half*16];
                #pragma unroll
                for (int c = 0; c < 4; c++) {
                    float4 vv = vp[c];
                    acc[c*4+0] = fmaf(e, vv.x, acc[c*4+0]);
                    acc[c*4+1] = fmaf(e, vv.y, acc[c*4+1]);
                    acc[c*4+2] = fmaf(e, vv.z, acc[c*4+2]);
                    acc[c*4+3] = fmaf(e, vv.w, acc[c*4+3]);
                }
            }
        }
    }

    const float inv = 1.0f / l;
    float4* outp = (float4*)&g_att[(size_t)(b*Nn + i)*Dd + h*DHd + half*16];
    #pragma unroll
    for (int c = 0; c < 4; c++)
        outp[c] = make_float4(acc[c*4+0]*inv, acc[c*4+1]*inv,
                              acc[c*4+2]*inv, acc[c*4+3]*inv);
}

// ---------------------------------------------------------------------------
// Kernel 3: FF GEMM + residual + bias.  y = x + ffb + att @ ff_w^T
// M=2048, O=512, K=512. Tile 128(m)x64(o), 256 threads, 8x4 microtile.
// ---------------------------------------------------------------------------
__global__ __launch_bounds__(256) void gemm_ff_kernel(
    const float* __restrict__ w, const float* __restrict__ xres,
    const float* __restrict__ ffb)
{
    __shared__ float As[16][132];
    __shared__ float Bs[16][68];
    const int tid = threadIdx.x;
    const int m0 = blockIdx.y * 128;
    const int o0 = blockIdx.x * 64;
    const int tx = tid & 15, ty = tid >> 4;

    float acc[8][4] = {};

    for (int k0 = 0; k0 < 512; k0 += 16) {
        #pragma unroll
        for (int r = 0; r < 2; r++) {
            int e = tid + r * 256;
            int row = e >> 2, c4 = (e & 3) << 2;
            float4 a = *(const float4*)&g_att[(m0 + row) * 512 + k0 + c4];
            As[c4+0][row] = a.x; As[c4+1][row] = a.y;
            As[c4+2][row] = a.z; As[c4+3][row] = a.w;
        }
        {   // B tile: 64x16 = 1024 floats, 1 float4/thread
            int row = tid >> 2, c4 = (tid & 3) << 2;
            float4 b = *(const float4*)&w[(o0 + row) * 512 + k0 + c4];
            Bs[c4+0][row] = b.x; Bs[c4+1][row] = b.y;
            Bs[c4+2][row] = b.z; Bs[c4+3][row] = b.w;
        }
        __syncthreads();
        #pragma unroll
        for (int kk = 0; kk < 16; kk++) {
            float a[8], b[4];
            *(float4*)&a[0] = *(const float4*)&As[kk][ty*8];
            *(float4*)&a[4] = *(const float4*)&As[kk][ty*8+4];
            *(float4*)&b[0] = *(const float4*)&Bs[kk][tx*4];
            #pragma unroll
            for (int i = 0; i < 8; i++)
                #pragma unroll
                for (int j = 0; j < 4; j++)
                    acc[i][j] = fmaf(a[i], b[j], acc[i][j]);
        }
        __syncthreads();
    }

    const int o_base = o0 + tx * 4;
    float4 fb = *(const float4*)&ffb[o_base];
    #pragma unroll
    for (int i = 0; i < 8; i++) {
        int m = m0 + ty * 8 + i;
        float4 xr = *(const float4*)&xres[m*512 + o_base];
        float4 o;
        o.x = acc[i][0] + xr.x + fb.x;
        o.y = acc[i][1] + xr.y + fb.y;
        o.z = acc[i][2] + xr.z + fb.z;
        o.w = acc[i][3] + xr.w + fb.w;
        *(float4*)&g_y[m*512 + o_base] = o;
    }
}

// ---------------------------------------------------------------------------
// Kernel 4: LayerNorm rows of g_y -> out.
// ---------------------------------------------------------------------------
__global__ __launch_bounds__(128) void ln_kernel(
    const float* __restrict__ lnw, const float* __restrict__ lnb,
    float* __restrict__ out)
{
    const int row = blockIdx.x;
    const int t = threadIdx.x;
    const float4 v = ((const float4*)&g_y[(size_t)row*512])[t];

    float s  = v.x + v.y + v.z + v.w;
    float ss = v.x*v.x + v.y*v.y + v.z*v.z + v.w*v.w;

    __shared__ float rs[4], rss[4];
    #pragma unroll
    for (int off = 16; off > 0; off >>= 1) {
        s  += __shfl_down_sync(0xffffffffu, s,  off);
        ss += __shfl_down_sync(0xffffffffu, ss, off);
    }
    if ((t & 31) == 0) { rs[t >> 5] = s; rss[t >> 5] = ss; }
    __syncthreads();
    float sum  = rs[0]  + rs[1]  + rs[2]  + rs[3];
    float sums = rss[0] + rss[1] + rss[2] + rss[3];

    const float mu   = sum  * (1.0f/512.0f);
    const float var  = sums * (1.0f/512.0f) - mu*mu;
    const float rstd = rsqrtf(var + 1e-5f);

    const float4 w = ((const float4*)lnw)[t];
    const float4 b = ((const float4*)lnb)[t];
    float4 o;
    o.x = (v.x - mu)*rstd*w.x + b.x;
    o.y = (v.y - mu)*rstd*w.y + b.y;
    o.z = (v.z - mu)*rstd*w.z + b.z;
    o.w = (v.w - mu)*rstd*w.w + b.w;
    ((float4*)&out[(size_t)row*512])[t] = o;
}

// ---------------------------------------------------------------------------
extern "C" void kernel_launch(void* const* d_in, const int* in_sizes, int n_in,
                              void* d_out, int out_size)
{
    const float* x         = (const float*)d_in[0];
    const float* pdist     = (const float*)d_in[1];
    const float* angle     = (const float*)d_in[2];
    const float* adj       = (const float*)d_in[3];
    const unsigned char* mask = (const unsigned char*)d_in[4];
    const float* gamma_p   = (const float*)d_in[5];
    const float* gamma_adj = (const float*)d_in[6];
    const float* w_bias    = (const float*)d_in[7];
    const float* att_w     = (const float*)d_in[8];
    const float* ff_w      = (const float*)d_in[9];
    const float* ff_b      = (const float*)d_in[10];
    const float* ln_w      = (const float*)d_in[11];
    const float* ln_b      = (const float*)d_in[12];
    float* out = (float*)d_out;

    gemm_qkv_kernel<<<dim3(1536/128, 2048/128), 256>>>(x, att_w);
    attn_kernel<<<dim3(Nn/64, Hh, Bsz), 128>>>(pdist, angle, adj, mask,
                                               gamma_p, gamma_adj, w_bias);
    gemm_ff_kernel<<<dim3(512/64, 2048/128), 256>>>(ff_w, x, ff_b);
    ln_kernel<<<Bsz*Nn, 128>>>(ln_w, ln_b, out);
}

// round 5
// speedup vs baseline: 2.5460x; 1.1952x over previous
#include <cuda_runtime.h>
#include <cuda_bf16.h>
#include <math.h>
#include <stdint.h>

#define Bsz 2
#define Nn  1024
#define Dd  512
#define Hh  16
#define DHd 32

// Scratch (device globals; no allocation allowed)
__device__ float g_q[Bsz*Hh*Nn*DHd];     // [B,H,N,DH]
__device__ float g_k[Bsz*Hh*Nn*DHd];     // [B,H,N,DH]
__device__ float g_v[Bsz*Hh*Nn*DHd];     // [B,H,N,DH]
__device__ float g_y[Bsz*Nn*Dd];         // pre-LN residual

// split-precision bf16 operands
__device__ __nv_bfloat16 g_xhi[Bsz*Nn*Dd],   g_xlo[Bsz*Nn*Dd];     // x
__device__ __nv_bfloat16 g_whi[1536*Dd],     g_wlo[1536*Dd];       // att_w
__device__ __nv_bfloat16 g_fwhi[Dd*Dd],      g_fwlo[Dd*Dd];        // ff_w
__device__ __nv_bfloat16 g_atthi[Bsz*Nn*Dd], g_attlo[Bsz*Nn*Dd];   // attn out

// ===================== warp-MMA helpers (no 'a' features) ====================
__device__ __forceinline__ uint32_t smem_u32(const void* p) {
    uint32_t a;
    asm("{ .reg .u64 t; cvta.to.shared.u64 t, %1; cvt.u32.u64 %0, t; }"
        : "=r"(a) : "l"(p));
    return a;
}
__device__ __forceinline__ void ldsm_x4(uint32_t* r, uint32_t addr) {
    asm volatile("ldmatrix.sync.aligned.m8n8.x4.shared.b16 {%0,%1,%2,%3}, [%4];"
        : "=r"(r[0]), "=r"(r[1]), "=r"(r[2]), "=r"(r[3]) : "r"(addr));
}
__device__ __forceinline__ void mma_16816(float* c, const uint32_t* a, const uint32_t* b) {
    asm volatile("mma.sync.aligned.m16n8k16.row.col.f32.bf16.bf16.f32 "
        "{%0,%1,%2,%3}, {%4,%5,%6,%7}, {%8,%9}, {%0,%1,%2,%3};"
        : "+f"(c[0]), "+f"(c[1]), "+f"(c[2]), "+f"(c[3])
        : "r"(a[0]), "r"(a[1]), "r"(a[2]), "r"(a[3]), "r"(b[0]), "r"(b[1]));
}

__device__ __forceinline__ uint32_t bfpack(__nv_bfloat16 a, __nv_bfloat16 b) {
    return (uint32_t)__bfloat16_as_ushort(a) | ((uint32_t)__bfloat16_as_ushort(b) << 16);
}
__device__ __forceinline__ void split4(float x0, float x1, float x2, float x3,
                                       uint2& uh, uint2& ul) {
    __nv_bfloat16 h0 = __float2bfloat16(x0), h1 = __float2bfloat16(x1);
    __nv_bfloat16 h2 = __float2bfloat16(x2), h3 = __float2bfloat16(x3);
    __nv_bfloat16 l0 = __float2bfloat16(x0 - __bfloat162float(h0));
    __nv_bfloat16 l1 = __float2bfloat16(x1 - __bfloat162float(h1));
    __nv_bfloat16 l2 = __float2bfloat16(x2 - __bfloat162float(h2));
    __nv_bfloat16 l3 = __float2bfloat16(x3 - __bfloat162float(h3));
    uh.x = bfpack(h0, h1); uh.y = bfpack(h2, h3);
    ul.x = bfpack(l0, l1); ul.y = bfpack(l2, l3);
}

// ---------------------------------------------------------------------------
// Kernel 0: fp32 -> bf16 hi/lo split (one pass per operand)
// ---------------------------------------------------------------------------
__global__ __launch_bounds__(256) void split_kernel(
    const float* __restrict__ src, __nv_bfloat16* __restrict__ hi,
    __nv_bfloat16* __restrict__ lo, int n4)
{
    int idx = blockIdx.x * 256 + threadIdx.x;
    if (idx >= n4) return;
    float4 v = ((const float4*)src)[idx];
    uint2 uh, ul;
    split4(v.x, v.y, v.z, v.w, uh, ul);
    *(uint2*)&hi[(size_t)idx*4] = uh;
    *(uint2*)&lo[(size_t)idx*4] = ul;
}

// ---------------------------------------------------------------------------
// Templated MMA mainloop: acc[MFR][4][4] += A[m0:,:512] * B[o0:,:512]^T
// (split: Ahi*Bhi + Ahi*Blo + Alo*Bhi).  256 threads, 8 warps (2m x 4n).
// Warp tile: (MFR*16) x 32.  CTA tile: (MFR*32) x 128.  K chunk 32.
// SMEM: XOR-swizzled, 64B rows, conflict-free for ldmatrix + stores.
// ---------------------------------------------------------------------------
template<int MFR>
__device__ __forceinline__ void mma_mainloop(
    const __nv_bfloat16* __restrict__ gAhi, const __nv_bfloat16* __restrict__ gAlo,
    const __nv_bfloat16* __restrict__ gBhi, const __nv_bfloat16* __restrict__ gBlo,
    int m0, int o0, char* smem, float (&acc)[MFR][4][4])
{
    constexpr int MT = MFR * 32;               // A tile rows
    constexpr int S_AHI = 0;
    constexpr int S_ALO = MT * 64;
    constexpr int S_BHI = 2 * MT * 64;
    constexpr int S_BLO = 2 * MT * 64 + 8192;
    const int tid = threadIdx.x;
    const int warp = tid >> 5, lane = tid & 31;
    const int wm = warp >> 2, wn = warp & 3;
    const uint32_t sb = smem_u32(smem);

    uint4 rAh[MFR/2], rAl[MFR/2], rBh[2], rBl[2];

    #define LOAD_CHUNK(kc) do { \
        _Pragma("unroll") \
        for (int i = 0; i < MFR/2; i++) { \
            int u = tid + i*256; \
            int row = u >> 2, c8 = (u & 3) * 8; \
            size_t g = (size_t)(m0 + row)*512 + (kc)*32 + c8; \
            rAh[i] = *(const uint4*)&gAhi[g]; \
            rAl[i] = *(const uint4*)&gAlo[g]; \
        } \
        _Pragma("unroll") \
        for (int i = 0; i < 2; i++) { \
            int u = tid + i*256; \
            int row = u >> 2, c8 = (u & 3) * 8; \
            size_t g = (size_t)(o0 + row)*512 + (kc)*32 + c8; \
            rBh[i] = *(const uint4*)&gBhi[g]; \
            rBl[i] = *(const uint4*)&gBlo[g]; \
        } \
    } while (0)

    #define STORE_CHUNK() do { \
        _Pragma("unroll") \
        for (int i = 0; i < MFR/2; i++) { \
            int u = tid + i*256; \
            int row = u >> 2, q = u & 3; \
            uint32_t off = row*64 + ((q ^ ((row>>1)&3)) << 4); \
            *(uint4*)(smem + S_AHI + off) = rAh[i]; \
            *(uint4*)(smem + S_ALO + off) = rAl[i]; \
        } \
        _Pragma("unroll") \
        for (int i = 0; i < 2; i++) { \
            int u = tid + i*256; \
            int row = u >> 2, q = u & 3; \
            uint32_t off = row*64 + ((q ^ ((row>>1)&3)) << 4); \
            *(uint4*)(smem + S_BHI + off) = rBh[i]; \
            *(uint4*)(smem + S_BLO + off) = rBl[i]; \
        } \
    } while (0)

    LOAD_CHUNK(0);
    STORE_CHUNK();
    __syncthreads();

    for (int kc = 0; kc < 16; kc++) {
        if (kc < 15) LOAD_CHUNK(kc + 1);
        #pragma unroll
        for (int ks = 0; ks < 2; ks++) {
            uint32_t bh[4][2], bl[4][2];
            #pragma unroll
            for (int p = 0; p < 2; p++) {
                int nrow = wn*32 + p*16 + (lane & 7) + ((lane >> 4) << 3);
                int qb = ks*2 + ((lane >> 3) & 1);
                uint32_t off = nrow*64 + ((qb ^ ((nrow>>1)&3)) << 4);
                uint32_t r[4];
                ldsm_x4(r, sb + S_BHI + off);
                bh[2*p][0] = r[0]; bh[2*p][1] = r[1];
                bh[2*p+1][0] = r[2]; bh[2*p+1][1] = r[3];
                ldsm_x4(r, sb + S_BLO + off);
                bl[2*p][0] = r[0]; bl[2*p][1] = r[1];
                bl[2*p+1][0] = r[2]; bl[2*p+1][1] = r[3];
            }
            #pragma unroll
            for (int mf = 0; mf < MFR; mf++) {
                int arow = wm*(MFR*16) + mf*16 + (lane & 15);
                int qb = ks*2 + (lane >> 4);
                uint32_t off = arow*64 + ((qb ^ ((arow>>1)&3)) << 4);
                uint32_t ah[4], al[4];
                ldsm_x4(ah, sb + S_AHI + off);
                ldsm_x4(al, sb + S_ALO + off);
                #pragma unroll
                for (int nf = 0; nf < 4; nf++) {
                    mma_16816(acc[mf][nf], ah, bh[nf]);
                    mma_16816(acc[mf][nf], ah, bl[nf]);
                    mma_16816(acc[mf][nf], al, bh[nf]);
                }
            }
        }
        __syncthreads();
        if (kc < 15) { STORE_CHUNK(); __syncthreads(); }
    }
    #undef LOAD_CHUNK
    #undef STORE_CHUNK
}

// ---------------------------------------------------------------------------
// Kernel 1: QKV GEMM (mma.sync).  grid (1536/128, 2048/128) = (12,16).
// ---------------------------------------------------------------------------
__global__ __launch_bounds__(256) void gemm_qkv_mma()
{
    extern __shared__ __align__(16) char smem[];
    const int m0 = blockIdx.y * 128, o0 = blockIdx.x * 128;
    float acc[4][4][4] = {};
    mma_mainloop<4>(g_xhi, g_xlo, g_whi, g_wlo, m0, o0, smem, acc);

    const int tid = threadIdx.x, warp = tid >> 5, lane = tid & 31;
    const int wm = warp >> 2, wn = warp & 3;
    const int bb = m0 >> 10;
    #pragma unroll
    for (int mf = 0; mf < 4; mf++) {
        int r0 = m0 + wm*64 + mf*16 + (lane >> 2);
        #pragma unroll
        for (int nf = 0; nf < 4; nf++) {
            int o = o0 + wn*32 + nf*8 + (lane & 3)*2;
            int which = o >> 9, h = (o >> 5) & 15, d = o & 31;
            float* dst = (which == 0) ? g_q : ((which == 1) ? g_k : g_v);
            size_t e0 = ((size_t)(bb*Hh + h)*Nn + (r0 & 1023))*DHd + d;
            size_t e1 = ((size_t)(bb*Hh + h)*Nn + ((r0 + 8) & 1023))*DHd + d;
            *(float2*)&dst[e0] = make_float2(acc[mf][nf][0], acc[mf][nf][1]);
            *(float2*)&dst[e1] = make_float2(acc[mf][nf][2], acc[mf][nf][3]);
        }
    }
}

// ---------------------------------------------------------------------------
// Kernel 3: FF GEMM + residual + bias.  grid (512/128, 2048/64) = (4,32).
// ---------------------------------------------------------------------------
__global__ __launch_bounds__(256) void gemm_ff_mma(
    const float* __restrict__ xres, const float* __restrict__ ffb)
{
    extern __shared__ __align__(16) char smem[];
    const int m0 = blockIdx.y * 64, o0 = blockIdx.x * 128;
    float acc[2][4][4] = {};
    mma_mainloop<2>(g_atthi, g_attlo, g_fwhi, g_fwlo, m0, o0, smem, acc);

    const int tid = threadIdx.x, warp = tid >> 5, lane = tid & 31;
    const int wm = warp >> 2, wn = warp & 3;
    #pragma unroll
    for (int mf = 0; mf < 2; mf++) {
        int r0 = m0 + wm*32 + mf*16 + (lane >> 2);
        #pragma unroll
        for (int nf = 0; nf < 4; nf++) {
            int o = o0 + wn*32 + nf*8 + (lane & 3)*2;
            float2 fb = *(const float2*)&ffb[o];
            float2 x0 = *(const float2*)&xres[(size_t)r0*512 + o];
            float2 x1 = *(const float2*)&xres[(size_t)(r0+8)*512 + o];
            *(float2*)&g_y[(size_t)r0*512 + o] = make_float2(
                acc[mf][nf][0] + x0.x + fb.x, acc[mf][nf][1] + x0.y + fb.y);
            *(float2*)&g_y[(size_t)(r0+8)*512 + o] = make_float2(
                acc[mf][nf][2] + x1.x + fb.x, acc[mf][nf][3] + x1.y + fb.y);
        }
    }
}

// ---------------------------------------------------------------------------
// Kernel 2: Fused attention (R3 structure). Epilogue writes split bf16.
// ---------------------------------------------------------------------------
__global__ __launch_bounds__(128) void attn_kernel(
    const float* __restrict__ pdist, const float* __restrict__ angle,
    const float* __restrict__ adj,   const unsigned char* __restrict__ mask,
    const float* __restrict__ gamma_p, const float* __restrict__ gamma_adj,
    const float* __restrict__ w_bias)
{
    const int b = blockIdx.z;
    const int h = blockIdx.y;
    const int t = threadIdx.x;
    const int qi = t >> 1;
    const int half = t & 1;
    const int i = blockIdx.x * 64 + qi;

    __shared__ float sK[32][32];
    __shared__ float sV[32][32];

    const float SCALE = 0.17677669529663689f;
    float q[16];
    {
        const float4* q4 = (const float4*)&g_q[(((b*Hh + h)*Nn) + i)*DHd + half*16];
        #pragma unroll
        for (int c = 0; c < 4; c++) {
            float4 v = q4[c];
            q[c*4+0] = v.x * SCALE; q[c*4+1] = v.y * SCALE;
            q[c*4+2] = v.z * SCALE; q[c*4+3] = v.w * SCALE;
        }
    }
    const float gp  = gamma_p[h];
    const float ga  = gamma_adj[h];
    const float wb0 = w_bias[h*2+0];
    const float wb1 = w_bias[h*2+1];

    const float* Kb = &g_k[((b*Hh + h)*Nn)*DHd];
    const float* Vb = &g_v[((b*Hh + h)*Nn)*DHd];
    const float* pd = pdist + (b*Nn + i)*Nn;
    const float* aj = adj   + (b*Nn + i)*Nn;
    const float* an = angle + (size_t)(b*Nn + i)*Nn*2;
    const unsigned char* mk = mask + b*Nn;

    float acc[16] = {};
    float l = 0.f;

    for (int j0 = 0; j0 < Nn; j0 += 32) {
        __syncthreads();
        {
            const float4* gK = (const float4*)(Kb + j0*DHd);
            const float4* gV = (const float4*)(Vb + j0*DHd);
            float4* dK = (float4*)sK;
            float4* dV = (float4*)sV;
            dK[t]       = gK[t];
            dK[t + 128] = gK[t + 128];
            dV[t]       = gV[t];
            dV[t + 128] = gV[t + 128];
        }
        __syncthreads();

        const float4* pdp = (const float4*)(pd + j0);
        const float4* ajp = (const float4*)(aj + j0);
        const float4* anp = (const float4*)(an + 2*j0);
        #pragma unroll
        for (int c8 = 0; c8 < 4; c8++) {
            float pdv[8], ajv[8], anv[16];
            *(float4*)&pdv[0]  = pdp[2*c8];     *(float4*)&pdv[4]  = pdp[2*c8+1];
            *(float4*)&ajv[0]  = ajp[2*c8];     *(float4*)&ajv[4]  = ajp[2*c8+1];
            *(float4*)&anv[0]  = anp[4*c8];     *(float4*)&anv[4]  = anp[4*c8+1];
            *(float4*)&anv[8]  = anp[4*c8+2];   *(float4*)&anv[12] = anp[4*c8+3];
            #pragma unroll
            for (int jj = 0; jj < 8; jj++) {
                const int j = c8*8 + jj;
                const float4* kp = (const float4*)&sK[j][half*16];
                float s = 0.f;
                #pragma unroll
                for (int c = 0; c < 4; c++) {
                    float4 kv = kp[c];
                    s = fmaf(q[c*4+0], kv.x, s);
                    s = fmaf(q[c*4+1], kv.y, s);
                    s = fmaf(q[c*4+2], kv.z, s);
                    s = fmaf(q[c*4+3], kv.w, s);
                }
                s += __shfl_xor_sync(0xffffffffu, s, 1);
                s = fmaf(wb0, anv[2*jj],   s);
                s = fmaf(wb1, anv[2*jj+1], s);
                s = fmaf(ga,  ajv[jj],     s);
                s = fmaf(-gp, pdv[jj],     s);
                if (mk[j0 + j]) s = -1e9f;
                float e = __expf(s);
                l += e;
                const float4* vp = (const float4*)&sV[j][half*16];
                #pragma unroll
                for (int c = 0; c < 4; c++) {
                    float4 vv = vp[c];
                    acc[c*4+0] = fmaf(e, vv.x, acc[c*4+0]);
                    acc[c*4+1] = fmaf(e, vv.y, acc[c*4+1]);
                    acc[c*4+2] = fmaf(e, vv.z, acc[c*4+2]);
                    acc[c*4+3] = fmaf(e, vv.w, acc[c*4+3]);
                }
            }
        }
    }

    const float inv = 1.0f / l;
    const size_t base = (size_t)(b*Nn + i)*Dd + h*DHd + half*16;
    #pragma unroll
    for (int c = 0; c < 4; c++) {
        uint2 uh, ul;
        split4(acc[c*4+0]*inv, acc[c*4+1]*inv, acc[c*4+2]*inv, acc[c*4+3]*inv, uh, ul);
        *(uint2*)&g_atthi[base + c*4] = uh;
        *(uint2*)&g_attlo[base + c*4] = ul;
    }
}

// ---------------------------------------------------------------------------
// Kernel 4: LayerNorm rows of g_y -> out.
// ---------------------------------------------------------------------------
__global__ __launch_bounds__(128) void ln_kernel(
    const float* __restrict__ lnw, const float* __restrict__ lnb,
    float* __restrict__ out)
{
    const int row = blockIdx.x;
    const int t = threadIdx.x;
    const float4 v = ((const float4*)&g_y[(size_t)row*512])[t];

    float s  = v.x + v.y + v.z + v.w;
    float ss = v.x*v.x + v.y*v.y + v.z*v.z + v.w*v.w;

    __shared__ float rs[4], rss[4];
    #pragma unroll
    for (int off = 16; off > 0; off >>= 1) {
        s  += __shfl_down_sync(0xffffffffu, s,  off);
        ss += __shfl_down_sync(0xffffffffu, ss, off);
    }
    if ((t & 31) == 0) { rs[t >> 5] = s; rss[t >> 5] = ss; }
    __syncthreads();
    float sum  = rs[0]  + rs[1]  + rs[2]  + rs[3];
    float sums = rss[0] + rss[1] + rss[2] + rss[3];

    const float mu   = sum  * (1.0f/512.0f);
    const float var  = sums * (1.0f/512.0f) - mu*mu;
    const float rstd = rsqrtf(var + 1e-5f);

    const float4 w = ((const float4*)lnw)[t];
    const float4 b = ((const float4*)lnb)[t];
    float4 o;
    o.x = (v.x - mu)*rstd*w.x + b.x;
    o.y = (v.y - mu)*rstd*w.y + b.y;
    o.z = (v.z - mu)*rstd*w.z + b.z;
    o.w = (v.w - mu)*rstd*w.w + b.w;
    ((float4*)&out[(size_t)row*512])[t] = o;
}

// ---------------------------------------------------------------------------
extern "C" void kernel_launch(void* const* d_in, const int* in_sizes, int n_in,
                              void* d_out, int out_size)
{
    const float* x         = (const float*)d_in[0];
    const float* pdist     = (const float*)d_in[1];
    const float* angle     = (const float*)d_in[2];
    const float* adj       = (const float*)d_in[3];
    const unsigned char* mask = (const unsigned char*)d_in[4];
    const float* gamma_p   = (const float*)d_in[5];
    const float* gamma_adj = (const float*)d_in[6];
    const float* w_bias    = (const float*)d_in[7];
    const float* att_w     = (const float*)d_in[8];
    const float* ff_w      = (const float*)d_in[9];
    const float* ff_b      = (const float*)d_in[10];
    const float* ln_w      = (const float*)d_in[11];
    const float* ln_b      = (const float*)d_in[12];
    float* out = (float*)d_out;

    __nv_bfloat16 *xhi, *xlo, *whi, *wlo, *fwhi, *fwlo;
    cudaGetSymbolAddress((void**)&xhi,  g_xhi);
    cudaGetSymbolAddress((void**)&xlo,  g_xlo);
    cudaGetSymbolAddress((void**)&whi,  g_whi);
    cudaGetSymbolAddress((void**)&wlo,  g_wlo);
    cudaGetSymbolAddress((void**)&fwhi, g_fwhi);
    cudaGetSymbolAddress((void**)&fwlo, g_fwlo);

    // Pre-split fp32 operands into bf16 hi/lo
    split_kernel<<<(Bsz*Nn*Dd/4 + 255)/256, 256>>>(x,     xhi,  xlo,  Bsz*Nn*Dd/4);
    split_kernel<<<(1536*Dd/4  + 255)/256, 256>>>(att_w, whi,  wlo,  1536*Dd/4);
    split_kernel<<<(Dd*Dd/4    + 255)/256, 256>>>(ff_w,  fwhi, fwlo, Dd*Dd/4);

    gemm_qkv_mma<<<dim3(1536/128, 2048/128), 256, 32768>>>();
    attn_kernel<<<dim3(Nn/64, Hh, Bsz), 128>>>(pdist, angle, adj, mask,
                                               gamma_p, gamma_adj, w_bias);
    gemm_ff_mma<<<dim3(512/128, 2048/64), 256, 24576>>>(x, ff_b);
    ln_kernel<<<Bsz*Nn, 128>>>(ln_w, ln_b, out);
}

// round 6
// speedup vs baseline: 6.0578x; 2.3794x over previous
#include <cuda_runtime.h>
#include <cuda_bf16.h>
#include <math.h>
#include <stdint.h>

#define Bsz 2
#define Nn  1024
#define Dd  512
#define Hh  16
#define DHd 32

// Scratch (device globals; no allocation allowed)
__device__ float g_y[Bsz*Nn*Dd];         // pre-LN residual

// split-precision bf16 operands
__device__ __nv_bfloat16 g_xhi[Bsz*Nn*Dd],   g_xlo[Bsz*Nn*Dd];     // x
__device__ __nv_bfloat16 g_whi[1536*Dd],     g_wlo[1536*Dd];       // att_w
__device__ __nv_bfloat16 g_fwhi[Dd*Dd],      g_fwlo[Dd*Dd];        // ff_w
__device__ __nv_bfloat16 g_atthi[Bsz*Nn*Dd], g_attlo[Bsz*Nn*Dd];   // attn out
// Q/K/V in bf16 hi/lo, [B,H,N,32]; Q pre-scaled by 1/sqrt(32)
__device__ __nv_bfloat16 g_qhi[Bsz*Hh*Nn*DHd], g_qlo[Bsz*Hh*Nn*DHd];
__device__ __nv_bfloat16 g_khi[Bsz*Hh*Nn*DHd], g_klo[Bsz*Hh*Nn*DHd];
__device__ __nv_bfloat16 g_vhi[Bsz*Hh*Nn*DHd], g_vlo[Bsz*Hh*Nn*DHd];

// ===================== warp-MMA helpers ====================================
__device__ __forceinline__ uint32_t smem_u32(const void* p) {
    uint32_t a;
    asm("{ .reg .u64 t; cvta.to.shared.u64 t, %1; cvt.u32.u64 %0, t; }"
        : "=r"(a) : "l"(p));
    return a;
}
__device__ __forceinline__ void ldsm_x4(uint32_t* r, uint32_t addr) {
    asm volatile("ldmatrix.sync.aligned.m8n8.x4.shared.b16 {%0,%1,%2,%3}, [%4];"
        : "=r"(r[0]), "=r"(r[1]), "=r"(r[2]), "=r"(r[3]) : "r"(addr));
}
__device__ __forceinline__ void ldsm_x4_t(uint32_t* r, uint32_t addr) {
    asm volatile("ldmatrix.sync.aligned.m8n8.x4.trans.shared.b16 {%0,%1,%2,%3}, [%4];"
        : "=r"(r[0]), "=r"(r[1]), "=r"(r[2]), "=r"(r[3]) : "r"(addr));
}
__device__ __forceinline__ void mma_16816(float* c, const uint32_t* a, const uint32_t* b) {
    asm volatile("mma.sync.aligned.m16n8k16.row.col.f32.bf16.bf16.f32 "
        "{%0,%1,%2,%3}, {%4,%5,%6,%7}, {%8,%9}, {%0,%1,%2,%3};"
        : "+f"(c[0]), "+f"(c[1]), "+f"(c[2]), "+f"(c[3])
        : "r"(a[0]), "r"(a[1]), "r"(a[2]), "r"(a[3]), "r"(b[0]), "r"(b[1]));
}
__device__ __forceinline__ uint32_t bfpack(__nv_bfloat16 a, __nv_bfloat16 b) {
    return (uint32_t)__bfloat16_as_ushort(a) | ((uint32_t)__bfloat16_as_ushort(b) << 16);
}
__device__ __forceinline__ void split2(float x0, float x1, uint32_t& uh, uint32_t& ul) {
    __nv_bfloat16 h0 = __float2bfloat16(x0), h1 = __float2bfloat16(x1);
    __nv_bfloat16 l0 = __float2bfloat16(x0 - __bfloat162float(h0));
    __nv_bfloat16 l1 = __float2bfloat16(x1 - __bfloat162float(h1));
    uh = bfpack(h0, h1); ul = bfpack(l0, l1);
}
__device__ __forceinline__ void split4(float x0, float x1, float x2, float x3,
                                       uint2& uh, uint2& ul) {
    split2(x0, x1, uh.x, ul.x);
    split2(x2, x3, uh.y, ul.y);
}

// ---------------------------------------------------------------------------
// Kernel 0: fp32 -> bf16 hi/lo split
// ---------------------------------------------------------------------------
__global__ __launch_bounds__(256) void split_kernel(
    const float* __restrict__ src, __nv_bfloat16* __restrict__ hi,
    __nv_bfloat16* __restrict__ lo, int n4)
{
    int idx = blockIdx.x * 256 + threadIdx.x;
    if (idx >= n4) return;
    float4 v = ((const float4*)src)[idx];
    uint2 uh, ul;
    split4(v.x, v.y, v.z, v.w, uh, ul);
    *(uint2*)&hi[(size_t)idx*4] = uh;
    *(uint2*)&lo[(size_t)idx*4] = ul;
}

// ---------------------------------------------------------------------------
// Templated MMA mainloop (unchanged from R5, proven).
// acc[MFR][4][4] += A[m0:,:512] * B[o0:,:512]^T, hi/lo split 3-MMA.
// CTA tile (MFR*32) x 128, 256 thr, 8 warps (2m x 4n).
// ---------------------------------------------------------------------------
template<int MFR>
__device__ __forceinline__ void mma_mainloop(
    const __nv_bfloat16* __restrict__ gAhi, const __nv_bfloat16* __restrict__ gAlo,
    const __nv_bfloat16* __restrict__ gBhi, const __nv_bfloat16* __restrict__ gBlo,
    int m0, int o0, char* smem, float (&acc)[MFR][4][4])
{
    constexpr int MT = MFR * 32;
    constexpr int S_AHI = 0;
    constexpr int S_ALO = MT * 64;
    constexpr int S_BHI = 2 * MT * 64;
    constexpr int S_BLO = 2 * MT * 64 + 8192;
    const int tid = threadIdx.x;
    const int warp = tid >> 5, lane = tid & 31;
    const int wm = warp >> 2, wn = warp & 3;
    const uint32_t sb = smem_u32(smem);

    uint4 rAh[MFR/2], rAl[MFR/2], rBh[2], rBl[2];

    #define LOAD_CHUNK(kc) do { \
        _Pragma("unroll") \
        for (int i = 0; i < MFR/2; i++) { \
            int u = tid + i*256; \
            int row = u >> 2, c8 = (u & 3) * 8; \
            size_t g = (size_t)(m0 + row)*512 + (kc)*32 + c8; \
            rAh[i] = *(const uint4*)&gAhi[g]; \
            rAl[i] = *(const uint4*)&gAlo[g]; \
        } \
        _Pragma("unroll") \
        for (int i = 0; i < 2; i++) { \
            int u = tid + i*256; \
            int row = u >> 2, c8 = (u & 3) * 8; \
            size_t g = (size_t)(o0 + row)*512 + (kc)*32 + c8; \
            rBh[i] = *(const uint4*)&gBhi[g]; \
            rBl[i] = *(const uint4*)&gBlo[g]; \
        } \
    } while (0)

    #define STORE_CHUNK() do { \
        _Pragma("unroll") \
        for (int i = 0; i < MFR/2; i++) { \
            int u = tid + i*256; \
            int row = u >> 2, q = u & 3; \
            uint32_t off = row*64 + ((q ^ ((row>>1)&3)) << 4); \
            *(uint4*)(smem + S_AHI + off) = rAh[i]; \
            *(uint4*)(smem + S_ALO + off) = rAl[i]; \
        } \
        _Pragma("unroll") \
        for (int i = 0; i < 2; i++) { \
            int u = tid + i*256; \
            int row = u >> 2, q = u & 3; \
            uint32_t off = row*64 + ((q ^ ((row>>1)&3)) << 4); \
            *(uint4*)(smem + S_BHI + off) = rBh[i]; \
            *(uint4*)(smem + S_BLO + off) = rBl[i]; \
        } \
    } while (0)

    LOAD_CHUNK(0);
    STORE_CHUNK();
    __syncthreads();

    for (int kc = 0; kc < 16; kc++) {
        if (kc < 15) LOAD_CHUNK(kc + 1);
        #pragma unroll
        for (int ks = 0; ks < 2; ks++) {
            uint32_t bh[4][2], bl[4][2];
            #pragma unroll
            for (int p = 0; p < 2; p++) {
                int nrow = wn*32 + p*16 + (lane & 7) + ((lane >> 4) << 3);
                int qb = ks*2 + ((lane >> 3) & 1);
                uint32_t off = nrow*64 + ((qb ^ ((nrow>>1)&3)) << 4);
                uint32_t r[4];
                ldsm_x4(r, sb + S_BHI + off);
                bh[2*p][0] = r[0]; bh[2*p][1] = r[1];
                bh[2*p+1][0] = r[2]; bh[2*p+1][1] = r[3];
                ldsm_x4(r, sb + S_BLO + off);
                bl[2*p][0] = r[0]; bl[2*p][1] = r[1];
                bl[2*p+1][0] = r[2]; bl[2*p+1][1] = r[3];
            }
            #pragma unroll
            for (int mf = 0; mf < MFR; mf++) {
                int arow = wm*(MFR*16) + mf*16 + (lane & 15);
                int qb = ks*2 + (lane >> 4);
                uint32_t off = arow*64 + ((qb ^ ((arow>>1)&3)) << 4);
                uint32_t ah[4], al[4];
                ldsm_x4(ah, sb + S_AHI + off);
                ldsm_x4(al, sb + S_ALO + off);
                #pragma unroll
                for (int nf = 0; nf < 4; nf++) {
                    mma_16816(acc[mf][nf], ah, bh[nf]);
                    mma_16816(acc[mf][nf], ah, bl[nf]);
                    mma_16816(acc[mf][nf], al, bh[nf]);
                }
            }
        }
        __syncthreads();
        if (kc < 15) { STORE_CHUNK(); __syncthreads(); }
    }
    #undef LOAD_CHUNK
    #undef STORE_CHUNK
}

// ---------------------------------------------------------------------------
// Kernel 1: QKV GEMM. CTA 64x128, grid (12, 32). Epilogue writes split bf16
// Q (pre-scaled), K, V in [B,H,N,32].
// ---------------------------------------------------------------------------
__global__ __launch_bounds__(256) void gemm_qkv_mma()
{
    extern __shared__ __align__(16) char smem[];
    const int m0 = blockIdx.y * 64, o0 = blockIdx.x * 128;
    float acc[2][4][4] = {};
    mma_mainloop<2>(g_xhi, g_xlo, g_whi, g_wlo, m0, o0, smem, acc);

    const float SCALE = 0.17677669529663689f;  // 1/sqrt(32)
    const int tid = threadIdx.x, warp = tid >> 5, lane = tid & 31;
    const int wm = warp >> 2, wn = warp & 3;
    const int bb = m0 >> 10;
    #pragma unroll
    for (int mf = 0; mf < 2; mf++) {
        int r0 = (m0 & 1023) + wm*32 + mf*16 + (lane >> 2);
        #pragma unroll
        for (int nf = 0; nf < 4; nf++) {
            int o = o0 + wn*32 + nf*8 + (lane & 3)*2;
            int which = o >> 9, h = (o >> 5) & 15, d = o & 31;
            __nv_bfloat16 *dhi, *dlo;
            float scl = 1.0f;
            if (which == 0)      { dhi = g_qhi; dlo = g_qlo; scl = SCALE; }
            else if (which == 1) { dhi = g_khi; dlo = g_klo; }
            else                 { dhi = g_vhi; dlo = g_vlo; }
            size_t e0 = ((size_t)(bb*Hh + h)*Nn + r0)*DHd + d;
            size_t e1 = e0 + 8*DHd;
            uint32_t uh, ul;
            split2(acc[mf][nf][0]*scl, acc[mf][nf][1]*scl, uh, ul);
            *(uint32_t*)&dhi[e0] = uh; *(uint32_t*)&dlo[e0] = ul;
            split2(acc[mf][nf][2]*scl, acc[mf][nf][3]*scl, uh, ul);
            *(uint32_t*)&dhi[e1] = uh; *(uint32_t*)&dlo[e1] = ul;
        }
    }
}

// ---------------------------------------------------------------------------
// Kernel 2: Tensor-core fused attention.
// Block = 64 queries x (head,batch), 128 thr (4 warps x 16 queries).
// QK: 3-split bf16 MMA; bias+mask+exp in-register; PV: 3-split MMA,
// V via ldmatrix.trans. Direct exp, normalize at end.
// ---------------------------------------------------------------------------
__global__ __launch_bounds__(128) void attn_mma(
    const float* __restrict__ pdist, const float* __restrict__ angle,
    const float* __restrict__ adj,   const unsigned char* __restrict__ mask,
    const float* __restrict__ gamma_p, const float* __restrict__ gamma_adj,
    const float* __restrict__ w_bias)
{
    __shared__ __align__(16) char sQh[4096];
    __shared__ __align__(16) char sQl[4096];
    __shared__ __align__(16) char sKh[4096];
    __shared__ __align__(16) char sKl[4096];
    __shared__ __align__(16) char sVh[4096];
    __shared__ __align__(16) char sVl[4096];
    __shared__ uint32_t smask[16];

    const int b = blockIdx.z, h = blockIdx.y;
    const int i0 = blockIdx.x * 64;
    const int t = threadIdx.x, w = t >> 5, lane = t & 31;

    const size_t ho = (size_t)(b*Hh + h)*Nn*DHd;
    const __nv_bfloat16* gQh = g_qhi + ho;
    const __nv_bfloat16* gQl = g_qlo + ho;
    const __nv_bfloat16* gKh = g_khi + ho;
    const __nv_bfloat16* gKl = g_klo + ho;
    const __nv_bfloat16* gVh = g_vhi + ho;
    const __nv_bfloat16* gVl = g_vlo + ho;

    const uint32_t sbQh = smem_u32(sQh), sbQl = smem_u32(sQl);
    const uint32_t sbKh = smem_u32(sKh), sbKl = smem_u32(sKl);
    const uint32_t sbVh = smem_u32(sVh), sbVl = smem_u32(sVl);

    // Load Q tile 64x32 hi/lo into swizzled smem
    #pragma unroll
    for (int u0 = 0; u0 < 2; u0++) {
        int u = t + u0*128;
        int row = u >> 2, q = u & 3;
        uint32_t off = row*64 + ((uint32_t)(q ^ ((row>>1)&3)) << 4);
        size_t g = (size_t)(i0 + row)*DHd + q*8;
        *(uint4*)(sQh + off) = *(const uint4*)&gQh[g];
        *(uint4*)(sQl + off) = *(const uint4*)&gQl[g];
    }
    __syncthreads();

    // Q fragments (held in registers for the whole sweep)
    uint32_t qh[2][4], ql[2][4];
    #pragma unroll
    for (int ks = 0; ks < 2; ks++) {
        int arow = w*16 + (lane & 15);
        int qb = ks*2 + (lane >> 4);
        uint32_t off = arow*64 + ((uint32_t)(qb ^ ((arow>>1)&3)) << 4);
        ldsm_x4(qh[ks], sbQh + off);
        ldsm_x4(ql[ks], sbQl + off);
    }

    const float gp  = gamma_p[h];
    const float ga  = gamma_adj[h];
    const float wb0 = w_bias[h*2+0];
    const float wb1 = w_bias[h*2+1];
    const unsigned char* mk = mask + b*Nn;

    const int qrow = w*16 + (lane >> 2);
    const size_t bi = ((size_t)b*Nn + i0 + qrow)*Nn;
    const float* pd0 = pdist + bi;   const float* pd1 = pd0 + 8*Nn;
    const float* aj0 = adj + bi;     const float* aj1 = aj0 + 8*Nn;
    const float* an0 = angle + bi*2; const float* an1 = an0 + 16*Nn;

    float o[4][4] = {};
    float l0 = 0.f, l1 = 0.f;

    for (int jt = 0; jt < 16; jt++) {
        const int j0 = jt*64;
        __syncthreads();
        #pragma unroll
        for (int u0 = 0; u0 < 2; u0++) {
            int u = t + u0*128;
            int row = u >> 2, q = u & 3;
            uint32_t off = row*64 + ((uint32_t)(q ^ ((row>>1)&3)) << 4);
            size_t g = (size_t)(j0 + row)*DHd + q*8;
            *(uint4*)(sKh + off) = *(const uint4*)&gKh[g];
            *(uint4*)(sKl + off) = *(const uint4*)&gKl[g];
            *(uint4*)(sVh + off) = *(const uint4*)&gVh[g];
            *(uint4*)(sVl + off) = *(const uint4*)&gVl[g];
        }
        if (t < 16) smask[t] = ((const uint32_t*)(mk + j0))[t];
        __syncthreads();

        #pragma unroll
        for (int kc = 0; kc < 4; kc++) {
            // ---- K fragments (16 keys = 2 n8 tiles, 2 dh k-chunks) ----
            uint32_t kh[2][2][2], kl[2][2][2];
            #pragma unroll
            for (int ks = 0; ks < 2; ks++) {
                int nrow = kc*16 + (lane & 7) + ((lane >> 4) << 3);
                int qb = ks*2 + ((lane >> 3) & 1);
                uint32_t off = nrow*64 + ((uint32_t)(qb ^ ((nrow>>1)&3)) << 4);
                uint32_t r[4];
                ldsm_x4(r, sbKh + off);
                kh[ks][0][0] = r[0]; kh[ks][0][1] = r[1];
                kh[ks][1][0] = r[2]; kh[ks][1][1] = r[3];
                ldsm_x4(r, sbKl + off);
                kl[ks][0][0] = r[0]; kl[ks][0][1] = r[1];
                kl[ks][1][0] = r[2]; kl[ks][1][1] = r[3];
            }
            // ---- QK^T scores ----
            float c[2][4] = {};
            #pragma unroll
            for (int nt2 = 0; nt2 < 2; nt2++)
                #pragma unroll
                for (int ks = 0; ks < 2; ks++) {
                    mma_16816(c[nt2], qh[ks], kh[ks][nt2]);
                    mma_16816(c[nt2], qh[ks], kl[ks][nt2]);
                    mma_16816(c[nt2], ql[ks], kh[ks][nt2]);
                }
            // ---- bias + mask + exp, pack P hi/lo A-fragments ----
            uint32_t ah[4], al[4];
            #pragma unroll
            for (int nt2 = 0; nt2 < 2; nt2++) {
                int jl = (kc*2 + nt2)*8 + (lane & 3)*2;
                int j = j0 + jl;
                float2 p0 = *(const float2*)(pd0 + j);
                float2 p1 = *(const float2*)(pd1 + j);
                float2 a0 = *(const float2*)(aj0 + j);
                float2 a1 = *(const float2*)(aj1 + j);
                float4 g0 = *(const float4*)(an0 + 2*j);
                float4 g1 = *(const float4*)(an1 + 2*j);
                float s0 = c[nt2][0] - gp*p0.x + wb0*g0.x + wb1*g0.y + ga*a0.x;
                float s1 = c[nt2][1] - gp*p0.y + wb0*g0.z + wb1*g0.w + ga*a0.y;
                float s2 = c[nt2][2] - gp*p1.x + wb0*g1.x + wb1*g1.y + ga*a1.x;
                float s3 = c[nt2][3] - gp*p1.y + wb0*g1.z + wb1*g1.w + ga*a1.y;
                float e0 = __expf(s0), e1 = __expf(s1);
                float e2 = __expf(s2), e3 = __expf(s3);
                const unsigned char* mb = (const unsigned char*)smask;
                if (mb[jl])     { e0 = 0.f; e2 = 0.f; }
                if (mb[jl + 1]) { e1 = 0.f; e3 = 0.f; }
                l0 += e0 + e1; l1 += e2 + e3;
                split2(e0, e1, ah[nt2*2 + 0], al[nt2*2 + 0]);   // row r
                split2(e2, e3, ah[nt2*2 + 1], al[nt2*2 + 1]);   // row r+8
            }
            // A-frag order: a0=klo(r), a1=klo(r+8), a2=khi(r), a3=khi(r+8)
            // nt2=0 -> keys 0-7 (klo), nt2=1 -> keys 8-15 (khi): already ordered.
            // ---- V fragments (trans) + PV ----
            uint32_t vh[4][2], vl[4][2];
            #pragma unroll
            for (int nh = 0; nh < 2; nh++) {
                int vrow = kc*16 + (lane & 15);
                int qv = nh*2 + (lane >> 4);
                uint32_t off = vrow*64 + ((uint32_t)(qv ^ ((vrow>>1)&3)) << 4);
                uint32_t r[4];
                ldsm_x4_t(r, sbVh + off);
                vh[nh*2+0][0] = r[0]; vh[nh*2+0][1] = r[1];
                vh[nh*2+1][0] = r[2]; vh[nh*2+1][1] = r[3];
                ldsm_x4_t(r, sbVl + off);
                vl[nh*2+0][0] = r[0]; vl[nh*2+0][1] = r[1];
                vl[nh*2+1][0] = r[2]; vl[nh*2+1][1] = r[3];
            }
            #pragma unroll
            for (int nv = 0; nv < 4; nv++) {
                mma_16816(o[nv], ah, vh[nv]);
                mma_16816(o[nv], al, vh[nv]);
                mma_16816(o[nv], ah, vl[nv]);
            }
        }
    }

    // normalize: reduce l across the quad that shares each row
    l0 += __shfl_xor_sync(0xffffffffu, l0, 1);
    l0 += __shfl_xor_sync(0xffffffffu, l0, 2);
    l1 += __shfl_xor_sync(0xffffffffu, l1, 1);
    l1 += __shfl_xor_sync(0xffffffffu, l1, 2);
    const float inv0 = 1.0f / l0, inv1 = 1.0f / l1;

    const int i_r = i0 + qrow;
    #pragma unroll
    for (int nv = 0; nv < 4; nv++) {
        int dh = nv*8 + (lane & 3)*2;
        size_t e0 = ((size_t)b*Nn + i_r)*Dd + h*DHd + dh;
        size_t e1 = e0 + 8*Dd;
        uint32_t uh, ul;
        split2(o[nv][0]*inv0, o[nv][1]*inv0, uh, ul);
        *(uint32_t*)&g_atthi[e0] = uh; *(uint32_t*)&g_attlo[e0] = ul;
        split2(o[nv][2]*inv1, o[nv][3]*inv1, uh, ul);
        *(uint32_t*)&g_atthi[e1] = uh; *(uint32_t*)&g_attlo[e1] = ul;
    }
}

// ---------------------------------------------------------------------------
// Kernel 3: FF GEMM + residual + bias (unchanged from R5).
// ---------------------------------------------------------------------------
__global__ __launch_bounds__(256) void gemm_ff_mma(
    const float* __restrict__ xres, const float* __restrict__ ffb)
{
    extern __shared__ __align__(16) char smem[];
    const int m0 = blockIdx.y * 64, o0 = blockIdx.x * 128;
    float acc[2][4][4] = {};
    mma_mainloop<2>(g_atthi, g_attlo, g_fwhi, g_fwlo, m0, o0, smem, acc);

    const int tid = threadIdx.x, warp = tid >> 5, lane = tid & 31;
    const int wm = warp >> 2, wn = warp & 3;
    #pragma unroll
    for (int mf = 0; mf < 2; mf++) {
        int r0 = m0 + wm*32 + mf*16 + (lane >> 2);
        #pragma unroll
        for (int nf = 0; nf < 4; nf++) {
            int o = o0 + wn*32 + nf*8 + (lane & 3)*2;
            float2 fb = *(const float2*)&ffb[o];
            float2 x0 = *(const float2*)&xres[(size_t)r0*512 + o];
            float2 x1 = *(const float2*)&xres[(size_t)(r0+8)*512 + o];
            *(float2*)&g_y[(size_t)r0*512 + o] = make_float2(
                acc[mf][nf][0] + x0.x + fb.x, acc[mf][nf][1] + x0.y + fb.y);
            *(float2*)&g_y[(size_t)(r0+8)*512 + o] = make_float2(
                acc[mf][nf][2] + x1.x + fb.x, acc[mf][nf][3] + x1.y + fb.y);
        }
    }
}

// ---------------------------------------------------------------------------
// Kernel 4: LayerNorm rows of g_y -> out.
// ---------------------------------------------------------------------------
__global__ __launch_bounds__(128) void ln_kernel(
    const float* __restrict__ lnw, const float* __restrict__ lnb,
    float* __restrict__ out)
{
    const int row = blockIdx.x;
    const int t = threadIdx.x;
    const float4 v = ((const float4*)&g_y[(size_t)row*512])[t];

    float s  = v.x + v.y + v.z + v.w;
    float ss = v.x*v.x + v.y*v.y + v.z*v.z + v.w*v.w;

    __shared__ float rs[4], rss[4];
    #pragma unroll
    for (int off = 16; off > 0; off >>= 1) {
        s  += __shfl_down_sync(0xffffffffu, s,  off);
        ss += __shfl_down_sync(0xffffffffu, ss, off);
    }
    if ((t & 31) == 0) { rs[t >> 5] = s; rss[t >> 5] = ss; }
    __syncthreads();
    float sum  = rs[0]  + rs[1]  + rs[2]  + rs[3];
    float sums = rss[0] + rss[1] + rss[2] + rss[3];

    const float mu   = sum  * (1.0f/512.0f);
    const float var  = sums * (1.0f/512.0f) - mu*mu;
    const float rstd = rsqrtf(var + 1e-5f);

    const float4 w = ((const float4*)lnw)[t];
    const float4 b = ((const float4*)lnb)[t];
    float4 o;
    o.x = (v.x - mu)*rstd*w.x + b.x;
    o.y = (v.y - mu)*rstd*w.y + b.y;
    o.z = (v.z - mu)*rstd*w.z + b.z;
    o.w = (v.w - mu)*rstd*w.w + b.w;
    ((float4*)&out[(size_t)row*512])[t] = o;
}

// ---------------------------------------------------------------------------
extern "C" void kernel_launch(void* const* d_in, const int* in_sizes, int n_in,
                              void* d_out, int out_size)
{
    const float* x         = (const float*)d_in[0];
    const float* pdist     = (const float*)d_in[1];
    const float* angle     = (const float*)d_in[2];
    const float* adj       = (const float*)d_in[3];
    const unsigned char* mask = (const unsigned char*)d_in[4];
    const float* gamma_p   = (const float*)d_in[5];
    const float* gamma_adj = (const float*)d_in[6];
    const float* w_bias    = (const float*)d_in[7];
    const float* att_w     = (const float*)d_in[8];
    const float* ff_w      = (const float*)d_in[9];
    const float* ff_b      = (const float*)d_in[10];
    const float* ln_w      = (const float*)d_in[11];
    const float* ln_b      = (const float*)d_in[12];
    float* out = (float*)d_out;

    __nv_bfloat16 *xhi, *xlo, *whi, *wlo, *fwhi, *fwlo;
    cudaGetSymbolAddress((void**)&xhi,  g_xhi);
    cudaGetSymbolAddress((void**)&xlo,  g_xlo);
    cudaGetSymbolAddress((void**)&whi,  g_whi);
    cudaGetSymbolAddress((void**)&wlo,  g_wlo);
    cudaGetSymbolAddress((void**)&fwhi, g_fwhi);
    cudaGetSymbolAddress((void**)&fwlo, g_fwlo);

    split_kernel<<<(Bsz*Nn*Dd/4 + 255)/256, 256>>>(x,     xhi,  xlo,  Bsz*Nn*Dd/4);
    split_kernel<<<(1536*Dd/4  + 255)/256, 256>>>(att_w, whi,  wlo,  1536*Dd/4);
    split_kernel<<<(Dd*Dd/4    + 255)/256, 256>>>(ff_w,  fwhi, fwlo, Dd*Dd/4);

    gemm_qkv_mma<<<dim3(1536/128, 2048/64), 256, 24576>>>();
    attn_mma<<<dim3(Nn/64, Hh, Bsz), 128>>>(pdist, angle, adj, mask,
                                            gamma_p, gamma_adj, w_bias);
    gemm_ff_mma<<<dim3(512/128, 2048/64), 256, 24576>>>(x, ff_b);
    ln_kernel<<<Bsz*Nn, 128>>>(ln_w, ln_b, out);
}